// round 17
// baseline (speedup 1.0000x reference)
#include <cuda_runtime.h>

// DilateAttention: B=8, C=384 (12 heads x 32), H=W=56, kernel 3x3, dilation 2, pad 2.
// q,k,v: [B, C, H, W] f32. out: [B, H, W, C] f32.
//
// R17: 2x2 pixel quads (y,y+2)x(x0,x0+1) per thread. Window-row sharing:
// top pixel needs rows {y-2,y,y+2}, bottom needs {y,y+2,y+4} -> rows y,y+2
// are loaded ONCE and serve both. 4 rows x 3 float2 x-windows = 12 LDG.64
// per channel per array for 4 pixels = 3 loads/px (R7: 4.5). Outer rows
// guarded (skip -> logit 0, matching unfold zero-pad); x-edges clamped +
// mask-zeroed on logits and weights. CC=4 chunks; __stwt streaming stores
// (R16 win); __ldcs on read-once q. Row pairing (4m+r, 4m+r+2) tiles all rows.

#define HD     32
#define HEADS  12
#define WD     56
#define HT     56
#define BD     8
#define HW     (WD * HT)
#define CTOT   384
#define XG     28
#define YP     28
#define NTHR   128
#define CC     4
#define NCH    (HD / CC)   // 8

__global__ __launch_bounds__(NTHR, 6)
void dilate_attn_kernel(const float* __restrict__ q,
                        const float* __restrict__ k,
                        const float* __restrict__ v,
                        float* __restrict__ out)
{
    const int gid  = blockIdx.x * NTHR + threadIdx.x;
    const int xg   = gid % XG;
    int r1         = gid / XG;
    const int j    = r1 % YP;
    int r2         = r1 / YP;
    const int head = r2 % HEADS;
    const int b    = r2 / HEADS;

    const int y  = 4 * (j >> 1) + (j & 1);   // rows y and y+2 both < 56
    const int x0 = xg * 2;

    const int base = (b * CTOT + head * HD) * HW;
    const int pix  = y * WD + x0;

    const bool yT = (y >= 2);          // row y-2 valid (top px outer row)
    const bool yB = (y + 4 < HT);      // row y+4 valid (bottom px outer row)
    const bool cL = (x0 >= 2);
    const bool cR = (x0 <= WD - 4);
    const int  xL = cL ? -2 : 0;
    const int  xR = cR ?  2 : 0;
    const float mL = cL ? 1.0f : 0.0f;
    const float mR = cR ? 1.0f : 0.0f;

    const float* qc = q + base + pix;
    const float* kc = k + base + pix;
    const float* vc = v + base + pix;

    const float scale = 0.17677669529663687f;  // 32^-0.5

    // logits: t = top pixels (row y, x0/x0+1), u = bottom pixels (row y+2)
    float t0[9], t1[9], u0[9], u1[9];
#pragma unroll
    for (int p = 0; p < 9; p++) { t0[p] = t1[p] = u0[p] = u1[p] = 0.0f; }

    // ================= K phase =================
#pragma unroll
    for (int ch = 0; ch < NCH; ch++) {
        float2 qt[CC], qu[CC];
#pragma unroll
        for (int c = 0; c < CC; c++) {
            qt[c] = __ldcs((const float2*)(qc + (ch * CC + c) * HW));
            qu[c] = __ldcs((const float2*)(qc + (ch * CC + c) * HW + 2 * WD));
            qt[c].x *= scale; qt[c].y *= scale;
            qu[c].x *= scale; qu[c].y *= scale;
        }
        const float* kb = kc + ch * CC * HW;

        // rows y (B) and y+2 (C): always valid, serve both pixel rows
#pragma unroll
        for (int c = 0; c < CC; c++) {
            const float* rB = kb + c * HW;
            float2 L = *(const float2*)(rB + xL);
            float2 Cc = *(const float2*)(rB);
            float2 R = *(const float2*)(rB + xR);
            t0[3] = fmaf(qt[c].x, L.x,  t0[3]); t1[3] = fmaf(qt[c].y, L.y,  t1[3]);
            t0[4] = fmaf(qt[c].x, Cc.x, t0[4]); t1[4] = fmaf(qt[c].y, Cc.y, t1[4]);
            t0[5] = fmaf(qt[c].x, R.x,  t0[5]); t1[5] = fmaf(qt[c].y, R.y,  t1[5]);
            u0[0] = fmaf(qu[c].x, L.x,  u0[0]); u1[0] = fmaf(qu[c].y, L.y,  u1[0]);
            u0[1] = fmaf(qu[c].x, Cc.x, u0[1]); u1[1] = fmaf(qu[c].y, Cc.y, u1[1]);
            u0[2] = fmaf(qu[c].x, R.x,  u0[2]); u1[2] = fmaf(qu[c].y, R.y,  u1[2]);

            const float* rC = rB + 2 * WD;
            float2 L2 = *(const float2*)(rC + xL);
            float2 C2 = *(const float2*)(rC);
            float2 R2 = *(const float2*)(rC + xR);
            t0[6] = fmaf(qt[c].x, L2.x, t0[6]); t1[6] = fmaf(qt[c].y, L2.y, t1[6]);
            t0[7] = fmaf(qt[c].x, C2.x, t0[7]); t1[7] = fmaf(qt[c].y, C2.y, t1[7]);
            t0[8] = fmaf(qt[c].x, R2.x, t0[8]); t1[8] = fmaf(qt[c].y, R2.y, t1[8]);
            u0[3] = fmaf(qu[c].x, L2.x, u0[3]); u1[3] = fmaf(qu[c].y, L2.y, u1[3]);
            u0[4] = fmaf(qu[c].x, C2.x, u0[4]); u1[4] = fmaf(qu[c].y, C2.y, u1[4]);
            u0[5] = fmaf(qu[c].x, R2.x, u0[5]); u1[5] = fmaf(qu[c].y, R2.y, u1[5]);
        }
        if (yT) {
#pragma unroll
            for (int c = 0; c < CC; c++) {
                const float* rA = kb + c * HW - 2 * WD;
                float2 L = *(const float2*)(rA + xL);
                float2 Cc = *(const float2*)(rA);
                float2 R = *(const float2*)(rA + xR);
                t0[0] = fmaf(qt[c].x, L.x,  t0[0]); t1[0] = fmaf(qt[c].y, L.y,  t1[0]);
                t0[1] = fmaf(qt[c].x, Cc.x, t0[1]); t1[1] = fmaf(qt[c].y, Cc.y, t1[1]);
                t0[2] = fmaf(qt[c].x, R.x,  t0[2]); t1[2] = fmaf(qt[c].y, R.y,  t1[2]);
            }
        }
        if (yB) {
#pragma unroll
            for (int c = 0; c < CC; c++) {
                const float* rD = kb + c * HW + 4 * WD;
                float2 L = *(const float2*)(rD + xL);
                float2 Cc = *(const float2*)(rD);
                float2 R = *(const float2*)(rD + xR);
                u0[6] = fmaf(qu[c].x, L.x,  u0[6]); u1[6] = fmaf(qu[c].y, L.y,  u1[6]);
                u0[7] = fmaf(qu[c].x, Cc.x, u0[7]); u1[7] = fmaf(qu[c].y, Cc.y, u1[7]);
                u0[8] = fmaf(qu[c].x, R.x,  u0[8]); u1[8] = fmaf(qu[c].y, R.y,  u1[8]);
            }
        }
    }

    // x-edge logit zeroing (unfold zero-pad -> logit exactly 0)
#pragma unroll
    for (int r = 0; r < 3; r++) {
        t0[r*3]   *= mL; t1[r*3]   *= mL; u0[r*3]   *= mL; u1[r*3]   *= mL;
        t0[r*3+2] *= mR; t1[r*3+2] *= mR; u0[r*3+2] *= mR; u1[r*3+2] *= mR;
    }

    // ================= softmax x4 (normalization folded into weights) ========
    {
        float mt0=-1e30f, mt1=-1e30f, mu0=-1e30f, mu1=-1e30f;
#pragma unroll
        for (int p = 0; p < 9; p++) {
            mt0 = fmaxf(mt0, t0[p]); mt1 = fmaxf(mt1, t1[p]);
            mu0 = fmaxf(mu0, u0[p]); mu1 = fmaxf(mu1, u1[p]);
        }
        float dt0=0.f, dt1=0.f, du0=0.f, du1=0.f;
#pragma unroll
        for (int p = 0; p < 9; p++) {
            t0[p] = __expf(t0[p]-mt0); dt0 += t0[p];
            t1[p] = __expf(t1[p]-mt1); dt1 += t1[p];
            u0[p] = __expf(u0[p]-mu0); du0 += u0[p];
            u1[p] = __expf(u1[p]-mu1); du1 += u1[p];
        }
        float it0 = 1.0f/dt0, it1 = 1.0f/dt1, iu0 = 1.0f/du0, iu1 = 1.0f/du1;
#pragma unroll
        for (int p = 0; p < 9; p++) {
            t0[p] *= it0; t1[p] *= it1; u0[p] *= iu0; u1[p] *= iu1;
        }
        // re-zero x-edge weights (clamped v loads would add center*w)
#pragma unroll
        for (int r = 0; r < 3; r++) {
            t0[r*3]   *= mL; t1[r*3]   *= mL; u0[r*3]   *= mL; u1[r*3]   *= mL;
            t0[r*3+2] *= mR; t1[r*3+2] *= mR; u0[r*3+2] *= mR; u1[r*3+2] *= mR;
        }
    }

    // ================= V phase =================
    const int obT = ((b * HT + y) * WD + x0) * CTOT + head * HD;
    const int obU = obT + 2 * WD * CTOT;

#pragma unroll
    for (int ch = 0; ch < NCH; ch++) {
        float at0[CC], at1[CC], au0[CC], au1[CC];
#pragma unroll
        for (int c = 0; c < CC; c++) { at0[c]=at1[c]=au0[c]=au1[c]=0.0f; }

        const float* vb = vc + ch * CC * HW;
#pragma unroll
        for (int c = 0; c < CC; c++) {
            const float* rB = vb + c * HW;
            float2 L = *(const float2*)(rB + xL);
            float2 Cc = *(const float2*)(rB);
            float2 R = *(const float2*)(rB + xR);
            at0[c] = fmaf(t0[3], L.x, fmaf(t0[4], Cc.x, fmaf(t0[5], R.x, at0[c])));
            at1[c] = fmaf(t1[3], L.y, fmaf(t1[4], Cc.y, fmaf(t1[5], R.y, at1[c])));
            au0[c] = fmaf(u0[0], L.x, fmaf(u0[1], Cc.x, fmaf(u0[2], R.x, au0[c])));
            au1[c] = fmaf(u1[0], L.y, fmaf(u1[1], Cc.y, fmaf(u1[2], R.y, au1[c])));

            const float* rC = rB + 2 * WD;
            float2 L2 = *(const float2*)(rC + xL);
            float2 C2 = *(const float2*)(rC);
            float2 R2 = *(const float2*)(rC + xR);
            at0[c] = fmaf(t0[6], L2.x, fmaf(t0[7], C2.x, fmaf(t0[8], R2.x, at0[c])));
            at1[c] = fmaf(t1[6], L2.y, fmaf(t1[7], C2.y, fmaf(t1[8], R2.y, at1[c])));
            au0[c] = fmaf(u0[3], L2.x, fmaf(u0[4], C2.x, fmaf(u0[5], R2.x, au0[c])));
            au1[c] = fmaf(u1[3], L2.y, fmaf(u1[4], C2.y, fmaf(u1[5], R2.y, au1[c])));
        }
        if (yT) {
#pragma unroll
            for (int c = 0; c < CC; c++) {
                const float* rA = vb + c * HW - 2 * WD;
                float2 L = *(const float2*)(rA + xL);
                float2 Cc = *(const float2*)(rA);
                float2 R = *(const float2*)(rA + xR);
                at0[c] = fmaf(t0[0], L.x, fmaf(t0[1], Cc.x, fmaf(t0[2], R.x, at0[c])));
                at1[c] = fmaf(t1[0], L.y, fmaf(t1[1], Cc.y, fmaf(t1[2], R.y, at1[c])));
            }
        }
        if (yB) {
#pragma unroll
            for (int c = 0; c < CC; c++) {
                const float* rD = vb + c * HW + 4 * WD;
                float2 L = *(const float2*)(rD + xL);
                float2 Cc = *(const float2*)(rD);
                float2 R = *(const float2*)(rD + xR);
                au0[c] = fmaf(u0[6], L.x, fmaf(u0[7], Cc.x, fmaf(u0[8], R.x, au0[c])));
                au1[c] = fmaf(u1[6], L.y, fmaf(u1[7], Cc.y, fmaf(u1[8], R.y, au1[c])));
            }
        }

        __stwt((float4*)(out + obT + ch * CC),        make_float4(at0[0], at0[1], at0[2], at0[3]));
        __stwt((float4*)(out + obT + CTOT + ch * CC), make_float4(at1[0], at1[1], at1[2], at1[3]));
        __stwt((float4*)(out + obU + ch * CC),        make_float4(au0[0], au0[1], au0[2], au0[3]));
        __stwt((float4*)(out + obU + CTOT + ch * CC), make_float4(au1[0], au1[1], au1[2], au1[3]));
    }
}

extern "C" void kernel_launch(void* const* d_in, const int* in_sizes, int n_in,
                              void* d_out, int out_size)
{
    const float* q = (const float*)d_in[0];
    const float* k = (const float*)d_in[1];
    const float* v = (const float*)d_in[2];
    float* out = (float*)d_out;

    int total  = BD * HEADS * YP * XG;   // 75264 threads (4 px each)
    int blocks = total / NTHR;           // 588
    dilate_attn_kernel<<<blocks, NTHR>>>(q, k, v, out);
}